// round 15
// baseline (speedup 1.0000x reference)
#include <cuda_runtime.h>

// S4D SSM layer, unified real-domain chunked scan, 2-threads-per-d split.
// Shapes hardcoded: L=4096, B=4, D=1024, N=16.
//
// Per state n: u_i = a u_{i-1} + b u_{i-2} + pr x_i - g x_{i-1}
// pass0: per-d coefficient tables (a, b, pr, -g) packed f32x2
// pass1: real local scan per chunk (zero init); 2 threads per d (8 states each)
// pass2: pair carry propagation across 64 chunks with companion C^64
// pass3: real scan with carried init + silu; 2 threads per d, shfl-pair reduce

#define NSTATE 16
#define PACKS  8
#define HP     4               // packs per thread (split)
#define TCH    64
#define NCH    64              // L / TCH
#define D_DIM  1024
#define B_SZ   4
#define XS     (B_SZ * D_DIM)  // float stride per timestep = 4096
#define SCALE_F 0.25f

typedef unsigned long long ull;

__device__ __forceinline__ ull pack2(float lo, float hi) {
    ull r; asm("mov.b64 %0, {%1,%2};" : "=l"(r) : "f"(lo), "f"(hi)); return r;
}
__device__ __forceinline__ void unpack2(ull v, float& a, float& b) {
    asm("mov.b64 {%0,%1}, %2;" : "=f"(a), "=f"(b) : "l"(v));
}
__device__ __forceinline__ ull fma2(ull a, ull b, ull c) {
    ull d; asm("fma.rn.f32x2 %0, %1, %2, %3;" : "=l"(d) : "l"(a), "l"(b), "l"(c)); return d;
}
__device__ __forceinline__ ull mul2(ull a, ull b) {
    ull d; asm("mul.rn.f32x2 %0, %1, %2;" : "=l"(d) : "l"(a), "l"(b)); return d;
}
__device__ __forceinline__ ull add2(ull a, ull b) {
    ull d; asm("add.rn.f32x2 %0, %1, %2;" : "=l"(d) : "l"(a), "l"(b)); return d;
}

// chunk-boundary u pairs: ((c*B + b)*NSTATE + n)*D + d ; float2 = (u_last, u_last-1)
__device__ float2 g_state[1 << 22];   // 32 MB static scratch

// coefficient tables, packed f32x2 per pack, [pack][d] layout (coalesced in d)
__device__ ull t_a [PACKS][D_DIM];   // 2 Re(q)
__device__ ull t_b [PACKS][D_DIM];   // -|q|^2
__device__ ull t_pr[PACKS][D_DIM];   // Re(p)
__device__ ull t_ng[PACKS][D_DIM];   // -Re(p conj(q))

__device__ __forceinline__ float silu_of(float z) {
    float sg = __fdividef(1.0f, 1.0f + __expf(-z));
    return z * sg;
}

// ---------------------------------------------------------------------------
// pass0: one thread per d — compute per-d coefficients, write tables.
// ---------------------------------------------------------------------------
__global__ void __launch_bounds__(128) s4d_pass0(
    const float* __restrict__ log_dt, const float* __restrict__ log_A_real,
    const float* __restrict__ A_imag, const float* __restrict__ Bparam,
    const float* __restrict__ Cparam)
{
    int d = blockIdx.x * 128 + threadIdx.x;
    float dt = __expf(log_dt[d]);

#pragma unroll
    for (int j = 0; j < PACKS; j++) {
        float av[2], bv[2], prv[2], ngv[2];
#pragma unroll
        for (int k = 0; k < 2; k++) {
            int n = d * NSTATE + 2 * j + k;
            float zr = -0.5f * dt * __expf(log_A_real[n]);
            float zi =  0.5f * dt * A_imag[n];
            float omz = 1.0f - zr;
            float inv = __fdividef(1.0f, omz * omz + zi * zi);
            float qr = (1.0f - zr * zr - zi * zi) * inv;
            float qi = 2.0f * zi * inv;
            float Br = Bparam[n * 2 + 0];
            float Bi = Bparam[n * 2 + 1];
            float Cr = Cparam[n * 2 + 0];
            float Ci = Cparam[n * 2 + 1];
            float ccr = Br * Cr - Bi * Ci;
            float cci = Br * Ci + Bi * Cr;
            float w = dt * SCALE_F * inv;
            float pr = w * (ccr * omz - cci * zi);
            float pi = w * (ccr * zi + cci * omz);

            av[k]  = 2.0f * qr;
            bv[k]  = -(qr * qr + qi * qi);
            prv[k] = pr;
            ngv[k] = -(pr * qr + pi * qi);
        }
        t_a [j][d] = pack2(av[0], av[1]);
        t_b [j][d] = pack2(bv[0], bv[1]);
        t_pr[j][d] = pack2(prv[0], prv[1]);
        t_ng[j][d] = pack2(ngv[0], ngv[1]);
    }
}

// half-width step (4 packs): VD := A*V + Bc*VD + Pr*xc + nG*xm
__device__ __forceinline__ void pstep_h(const ull* A, const ull* Bc,
                                        const ull* Pr, const ull* nG,
                                        const ull* V, ull* VD,
                                        float xc, float xm)
{
    ull Xc = pack2(xc, xc);
    ull Xm = pack2(xm, xm);
#pragma unroll
    for (int j = 0; j < HP; j++) {
        ull w = fma2(Pr[j], Xc, mul2(nG[j], Xm));
        ull t = fma2(Bc[j], VD[j], w);
        VD[j] = fma2(A[j], V[j], t);
    }
}

// half-width step with partial reduction: returns sum over this thread's 8 states
__device__ __forceinline__ float rstep_h(const ull* A, const ull* Bc,
                                         const ull* Pr, const ull* nG,
                                         const ull* V, ull* VD,
                                         float xc, float xm)
{
    ull Xc = pack2(xc, xc);
    ull Xm = pack2(xm, xm);
    ull acc0 = 0ull, acc1 = 0ull;
#pragma unroll
    for (int j = 0; j < HP; j++) {
        ull w  = fma2(Pr[j], Xc, mul2(nG[j], Xm));
        ull t  = fma2(Bc[j], VD[j], w);
        ull nv = fma2(A[j], V[j], t);
        VD[j] = nv;
        if (j & 1) acc1 = add2(acc1, nv);
        else       acc0 = add2(acc0, nv);
    }
    ull s = add2(acc0, acc1);
    float lo, hi; unpack2(s, lo, hi);
    return lo + hi;
}

// ---------------------------------------------------------------------------
// pass1: real local scan, zero-init pair, 2 threads per d (h = tid&1).
// ---------------------------------------------------------------------------
__global__ void __launch_bounds__(256, 3) s4d_pass1(const float* __restrict__ x)
{
    int t  = threadIdx.x;
    int h  = t & 1;
    int d  = blockIdx.x * 128 + (t >> 1);
    int b  = blockIdx.y;
    int c  = blockIdx.z;

    ull A[HP], Bc[HP], Pr[HP], nG[HP], U0[HP], U1[HP];
#pragma unroll
    for (int j = 0; j < HP; j++) {
        int jj = h * HP + j;
        A[j]  = t_a [jj][d];
        Bc[j] = t_b [jj][d];
        Pr[j] = t_pr[jj][d];
        nG[j] = t_ng[jj][d];
        U0[j] = 0ull; U1[j] = 0ull;
    }

    long long base = ((long long)(c * TCH) * B_SZ + b) * D_DIM + d;
    float xm = (c == 0) ? 0.0f : x[base - XS];
    const float* xq = x + base;

    for (int it = 0; it < 8; it++) {
        float xv[8];
#pragma unroll
        for (int u = 0; u < 8; u++)
            xv[u] = xq[(long long)u * XS];
        xq += 8 * XS;

#pragma unroll
        for (int u = 0; u < 8; u++) {
            float prev = (u == 0) ? xm : xv[u - 1];
            if (u & 1) pstep_h(A, Bc, Pr, nG, U1, U0, xv[u], prev);
            else       pstep_h(A, Bc, Pr, nG, U0, U1, xv[u], prev);
        }
        xm = xv[7];
    }

    // store this thread's 8 states: n = h*8 + 2j (+1)
    float2* st = g_state + (((long long)c * B_SZ + b) * NSTATE) * D_DIM + d;
#pragma unroll
    for (int j = 0; j < HP; j++) {
        float n0, n1, p0, p1;
        unpack2(U0[j], n0, n1);   // v_63
        unpack2(U1[j], p0, p1);   // v_62
        int n = h * 8 + 2 * j;
        st[(long long)n * D_DIM]       = make_float2(n0, p0);
        st[(long long)(n + 1) * D_DIM] = make_float2(n1, p1);
    }
}

// ---------------------------------------------------------------------------
// pass2: pair carry propagation with companion C^64, blocked 4x16.
// ---------------------------------------------------------------------------
__global__ void __launch_bounds__(256) s4d_pass2(
    const float* __restrict__ log_dt, const float* __restrict__ log_A_real,
    const float* __restrict__ A_imag)
{
    int id = blockIdx.x * 256 + threadIdx.x;
    int d = id % D_DIM;
    int n = (id / D_DIM) % NSTATE;
    int b = id / (D_DIM * NSTATE);

    float dt = __expf(log_dt[d]);
    float zr = -0.5f * dt * __expf(log_A_real[d * NSTATE + n]);
    float zi =  0.5f * dt * A_imag[d * NSTATE + n];
    float omz = 1.0f - zr;
    float inv = __fdividef(1.0f, omz * omz + zi * zi);
    float qr = (1.0f - zr * zr - zi * zi) * inv;
    float qi = 2.0f * zi * inv;

    // companion C = [[a, b],[1,0]]; M = C^64 via 6 squarings
    float m00 = 2.0f * qr, m01 = -(qr * qr + qi * qi);
    float m10 = 1.0f, m11 = 0.0f;
#pragma unroll
    for (int i = 0; i < 6; i++) {
        float n00 = m00 * m00 + m01 * m10;
        float n01 = m00 * m01 + m01 * m11;
        float n10 = m10 * m00 + m11 * m10;
        float n11 = m10 * m01 + m11 * m11;
        m00 = n00; m01 = n01; m10 = n10; m11 = n11;
    }

    long long base = ((long long)b * NSTATE + n) * D_DIM + d;
    const long long cstride = (long long)B_SZ * NSTATE * D_DIM;

    float tx = 0.0f, ty = 0.0f;   // carried true pair (u_last, u_last-1)
#pragma unroll 1
    for (int blk = 0; blk < 4; blk++) {
        long long c0 = (long long)blk * 16;
        float2 t[16];
#pragma unroll
        for (int i = 0; i < 16; i++)
            t[i] = g_state[base + (c0 + i) * cstride];
#pragma unroll
        for (int i = 0; i < 16; i++) {
            float nx = fmaf(m00, tx, fmaf(m01, ty, t[i].x));
            float ny = fmaf(m10, tx, fmaf(m11, ty, t[i].y));
            tx = nx; ty = ny;
            t[i] = make_float2(tx, ty);
        }
#pragma unroll
        for (int i = 0; i < 16; i++)
            g_state[base + (c0 + i) * cstride] = t[i];
    }
}

// ---------------------------------------------------------------------------
// pass3: real scan with carried (u_{-1}, u_{-2}) init, silu output.
// 2 threads per d; pair sum via shfl_xor(1); h==0 stores.
// ---------------------------------------------------------------------------
__global__ void __launch_bounds__(256, 3) s4d_pass3(
    const float* __restrict__ x, const float* __restrict__ Dparam,
    float* __restrict__ out)
{
    int t  = threadIdx.x;
    int h  = t & 1;
    int d  = blockIdx.x * 128 + (t >> 1);
    int b  = blockIdx.y;
    int c  = blockIdx.z;

    long long base = ((long long)(c * TCH) * B_SZ + b) * D_DIM + d;
    const float* xq = x + base;
    float* oq = out + base;
    float dpar = Dparam[d];

    ull A[HP], Bc[HP], Pr[HP], nG[HP], U0[HP], U1[HP];
#pragma unroll
    for (int j = 0; j < HP; j++) {
        int jj = h * HP + j;
        A[j]  = t_a [jj][d];
        Bc[j] = t_b [jj][d];
        Pr[j] = t_pr[jj][d];
        nG[j] = t_ng[jj][d];
    }

    float xm;
    if (c > 0) {
        const float2* st = g_state +
            (((long long)(c - 1) * B_SZ + b) * NSTATE) * D_DIM + d;
#pragma unroll
        for (int j = 0; j < HP; j++) {
            int n = h * 8 + 2 * j;
            float2 v0 = st[(long long)n * D_DIM];
            float2 v1 = st[(long long)(n + 1) * D_DIM];
            U0[j] = pack2(v0.x, v1.x);   // u_{-1}
            U1[j] = pack2(v0.y, v1.y);   // u_{-2}
        }
        xm = x[base - XS];
    } else {
#pragma unroll
        for (int j = 0; j < HP; j++) { U0[j] = 0ull; U1[j] = 0ull; }
        xm = 0.0f;
    }

    for (int it = 0; it < 8; it++) {
        float xv[8];
#pragma unroll
        for (int u = 0; u < 8; u++)
            xv[u] = xq[(long long)u * XS];
        xq += 8 * XS;

#pragma unroll
        for (int u = 0; u < 8; u++) {
            float prev = (u == 0) ? xm : xv[u - 1];
            float yp = (u & 1) ? rstep_h(A, Bc, Pr, nG, U1, U0, xv[u], prev)
                               : rstep_h(A, Bc, Pr, nG, U0, U1, xv[u], prev);
            float y = yp + __shfl_xor_sync(0xffffffffu, yp, 1);
            float z = silu_of(fmaf(xv[u], dpar, y));
            if (h == 0)
                oq[(long long)u * XS] = z;
        }
        xm = xv[7];
        oq += 8 * XS;
    }
}

extern "C" void kernel_launch(void* const* d_in, const int* in_sizes, int n_in,
                              void* d_out, int out_size)
{
    const float* x      = (const float*)d_in[0];
    const float* log_dt = (const float*)d_in[1];
    const float* lar    = (const float*)d_in[2];
    const float* aim    = (const float*)d_in[3];
    const float* Bp     = (const float*)d_in[4];
    const float* Cp     = (const float*)d_in[5];
    const float* Dp     = (const float*)d_in[6];
    float* out = (float*)d_out;

    s4d_pass0<<<D_DIM / 128, 128>>>(log_dt, lar, aim, Bp, Cp);

    dim3 blk(256);                      // 128 d per block, 2 threads per d
    dim3 grd(D_DIM / 128, B_SZ, NCH);   // (8, 4, 64) = 2048 blocks

    s4d_pass1<<<grd, blk>>>(x);

    int total2 = B_SZ * NSTATE * D_DIM;      // 65536
    s4d_pass2<<<total2 / 256, 256>>>(log_dt, lar, aim);

    s4d_pass3<<<grd, blk>>>(x, Dp, out);
}